// round 3
// baseline (speedup 1.0000x reference)
#include <cuda_runtime.h>
#include <math.h>

// Shapes (fixed by the problem)
#define BB     512
#define NSLOT  128
#define IN_    2048
#define MEM_   64
#define OUT_   2048
#define KTOT   2176   // IN + 2*MEM
#define NK1    16     // split-K factor for K1
#define NCOLS  130    // 64 (q) + 65 (xr) + 1 (xf)

// -------------------- device scratch (no allocations allowed) ----------------
__device__ float g_kpart[NK1 * BB * NCOLS];   // K1 partial sums  (~4.3 MB)
__device__ float g_wpack[IN_ * NCOLS];        // packed [W_ar | W_r_x | W_f_x]
__device__ float g_ar[BB * MEM_];             // active recall
__device__ float g_pr[BB * MEM_];             // passive recall

// ============================================================================
// K0: pack the x-side weight columns into one contiguous [2048 x 130] matrix
// ============================================================================
__global__ void pack_kernel(const float* __restrict__ W_ar,
                            const float* __restrict__ W_r,
                            const float* __restrict__ W_f) {
    int idx = blockIdx.x * 256 + threadIdx.x;
    if (idx >= IN_ * NCOLS) return;
    int k = idx / NCOLS;
    int j = idx - k * NCOLS;
    float w;
    if (j < 64)       w = W_ar[k * 64 + j];
    else if (j < 129) w = W_r[k * 65 + (j - 64)];
    else              w = W_f[k];
    g_wpack[idx] = w;
}

// ============================================================================
// K1: partial GEMM  x[512,2048] @ wpack[2048,130] -> g_kpart[16][512][130]
//     grid (16 m-tiles, 16 k-tiles), 160 threads (thread = output column)
// ============================================================================
__global__ void k1_kernel(const float* __restrict__ x) {
    const int mb = blockIdx.x;   // 0..15 -> rows mb*32..mb*32+31
    const int kb = blockIdx.y;   // 0..15 -> k range kb*128..
    __shared__ float xs[32][128];

    for (int i = threadIdx.x; i < 32 * 128; i += blockDim.x) {
        int m = i >> 7, k = i & 127;
        xs[m][k] = x[(mb * 32 + m) * IN_ + kb * 128 + k];
    }
    __syncthreads();

    const int j = threadIdx.x;
    if (j < NCOLS) {
        float acc[32];
#pragma unroll
        for (int m = 0; m < 32; m++) acc[m] = 0.f;
        const float* wp = g_wpack + (kb * 128) * NCOLS + j;
#pragma unroll 4
        for (int k = 0; k < 128; k++) {
            float w = wp[k * NCOLS];
#pragma unroll
            for (int m = 0; m < 32; m++) acc[m] = fmaf(xs[m][k], w, acc[m]);
        }
        float* outp = g_kpart + (kb * BB + mb * 32) * NCOLS + j;
#pragma unroll
        for (int m = 0; m < 32; m++) outp[m * NCOLS] = acc[m];
    }
}

// ============================================================================
// K2: one block per batch row. Fuses: K1 reduction (+bias), attention scores,
//     both softmaxes, active/passive recall, forget gate, memory @ W_r_m, and
//     the gated memory update. Writes new_memory and the recall vectors.
//     128 threads (thread = slot). Dynamic smem: mem tile + W_r_m tile.
// ============================================================================
#define K2_SMEM ((NSLOT * 65 + 64 * 68) * 4)   // 50688 bytes

__global__ void k2_kernel(const float* __restrict__ memory,
                          const float* __restrict__ b_ar,
                          const float* __restrict__ W_pr,
                          const float* __restrict__ b_pr,
                          const float* __restrict__ W_f,
                          const float* __restrict__ b_f,
                          const float* __restrict__ W_r,
                          const float* __restrict__ b_r,
                          float* __restrict__ new_memory) {
    extern __shared__ float dyn[];
    float* mem_s = dyn;                       // [128][65]  (padded rows)
    float* wrm   = dyn + NSLOT * 65;          // [64][68]   (cols 0..64 valid)

    __shared__ float sq[64];
    __shared__ float sxr[65];
    __shared__ float swfm[64];
    __shared__ float swpr[64];
    __shared__ float sscore[128];
    __shared__ float sp[128];
    __shared__ float red[128];
    __shared__ float sxf;

    const int b = blockIdx.x;
    const int t = threadIdx.x;

    // ---- reduce K1 split-K partials, add biases ----
    for (int jj = t; jj < NCOLS; jj += 128) {
        float s = 0.f;
#pragma unroll
        for (int kb = 0; kb < NK1; kb++) s += g_kpart[(kb * BB + b) * NCOLS + jj];
        if (jj < 64)       sq[jj] = s + b_ar[jj];
        else if (jj < 129) sxr[jj - 64] = s + b_r[jj - 64];
        else               sxf = s + b_f[0];
    }

    // ---- stage weights ----
    for (int i = t; i < 64 * 68; i += 128) {
        int k = i / 68, c = i - k * 68;
        wrm[i] = (c < 65) ? W_r[IN_ * 65 + k * 65 + c] : 0.f;
    }
    if (t < 64) { swfm[t] = W_f[IN_ + t]; swpr[t] = W_pr[t]; }

    // ---- stage memory[b] (padded to stride 65 for conflict-free reads) ----
    const float* mrow = memory + (size_t)b * (NSLOT * MEM_);
    for (int i = t; i < NSLOT * MEM_; i += 128)
        mem_s[(i >> 6) * 65 + (i & 63)] = mrow[i];
    __syncthreads();

    // ---- per-slot logits ----
    const float* my = mem_s + t * 65;
    float sc = 0.f, pl = 0.f;
#pragma unroll
    for (int k = 0; k < 64; k++) {
        float mv = my[k];
        sc = fmaf(mv, sq[k], sc);
        pl = fmaf(mv, swpr[k], pl);
    }
    pl += b_pr[0];

    // ---- softmax over slots: active scores ----
    red[t] = sc; __syncthreads();
    for (int s2 = 64; s2 > 0; s2 >>= 1) { if (t < s2) red[t] = fmaxf(red[t], red[t + s2]); __syncthreads(); }
    float mx = red[0]; __syncthreads();
    float e = expf(sc - mx);
    red[t] = e; __syncthreads();
    for (int s2 = 64; s2 > 0; s2 >>= 1) { if (t < s2) red[t] += red[t + s2]; __syncthreads(); }
    sscore[t] = e / red[0]; __syncthreads();

    // ---- softmax over slots: passive scores ----
    red[t] = pl; __syncthreads();
    for (int s2 = 64; s2 > 0; s2 >>= 1) { if (t < s2) red[t] = fmaxf(red[t], red[t + s2]); __syncthreads(); }
    float mx2 = red[0]; __syncthreads();
    float e2 = expf(pl - mx2);
    red[t] = e2; __syncthreads();
    for (int s2 = 64; s2 > 0; s2 >>= 1) { if (t < s2) red[t] += red[t + s2]; __syncthreads(); }
    sp[t] = e2 / red[0];
    __syncthreads();

    // ---- active / passive recall (column sums) ----
    if (t < 64) {
        float a = 0.f, p = 0.f;
#pragma unroll 4
        for (int n = 0; n < NSLOT; n++) {
            float mv = mem_s[n * 65 + t];
            a = fmaf(mv, sscore[n], a);
            p = fmaf(mv, sp[n], p);
        }
        g_ar[b * 64 + t] = a;
        g_pr[b * 64 + t] = p;
    }

    // ---- gated memory update: slot t ----
    float mreg[64];
#pragma unroll
    for (int k = 0; k < 64; k++) mreg[k] = my[k];

    float fl = sxf;
#pragma unroll
    for (int k = 0; k < 64; k++) fl = fmaf(mreg[k], swfm[k], fl);
    float fgt = 1.1f / (1.f + expf(-fl));

    float r64 = sxr[64];
#pragma unroll
    for (int k = 0; k < 64; k++) r64 = fmaf(mreg[k], wrm[k * 68 + 64], r64);

    __syncthreads();   // all reads of mem_s done; safe to overwrite with result

    for (int jb = 0; jb < 16; jb++) {
        float a0 = sxr[jb * 4 + 0], a1 = sxr[jb * 4 + 1];
        float a2 = sxr[jb * 4 + 2], a3 = sxr[jb * 4 + 3];
#pragma unroll
        for (int k = 0; k < 64; k++) {
            float4 w = *(const float4*)&wrm[k * 68 + jb * 4];
            float mv = mreg[k];
            a0 = fmaf(mv, w.x, a0);
            a1 = fmaf(mv, w.y, a1);
            a2 = fmaf(mv, w.z, a2);
            a3 = fmaf(mv, w.w, a3);
        }
        mem_s[t * 65 + jb * 4 + 0] = fmaf(mreg[jb * 4 + 0], fgt, r64 * a0);
        mem_s[t * 65 + jb * 4 + 1] = fmaf(mreg[jb * 4 + 1], fgt, r64 * a1);
        mem_s[t * 65 + jb * 4 + 2] = fmaf(mreg[jb * 4 + 2], fgt, r64 * a2);
        mem_s[t * 65 + jb * 4 + 3] = fmaf(mreg[jb * 4 + 3], fgt, r64 * a3);
    }
    __syncthreads();

    float* orow = new_memory + (size_t)b * (NSLOT * MEM_);
    for (int i = t; i < NSLOT * MEM_; i += 128)
        orow[i] = mem_s[(i >> 6) * 65 + (i & 63)];
}

// ============================================================================
// K3: output GEMM  [x | active | passive] (512x2176) @ W_o (2176x2048) + b_o
//     64x64 block tile, BK=16, 256 threads, 4x4 microtile, double-buffered.
// ============================================================================
__device__ __forceinline__ float loadA(const float* __restrict__ x, int m, int k) {
    if (k < IN_)        return __ldg(&x[m * IN_ + k]);
    if (k < IN_ + MEM_) return g_ar[m * MEM_ + (k - IN_)];
    return g_pr[m * MEM_ + (k - IN_ - MEM_)];
}

__global__ void __launch_bounds__(256) k3_kernel(const float* __restrict__ x,
                                                 const float* __restrict__ W_o,
                                                 const float* __restrict__ b_o,
                                                 float* __restrict__ out) {
    const int bx = blockIdx.x;   // 32 N-tiles
    const int by = blockIdx.y;   // 8  M-tiles
    const int tid = threadIdx.x;
    const int tx = tid & 15, ty = tid >> 4;

    __shared__ float As[2][16 * 68];
    __shared__ float Bs[2][16 * 68];

    const int am = tid >> 2;           // 0..63 (row within tile)
    const int ak = (tid & 3) * 4;      // 0,4,8,12
    const int bk = tid >> 4;           // 0..15
    const int bn = (tid & 15) * 4;     // 0..60
    const int row0 = by * 64;
    const int col0 = bx * 64;

    float areg[4];
    float4 breg;
    // prefetch tile 0
#pragma unroll
    for (int i = 0; i < 4; i++) areg[i] = loadA(x, row0 + am, ak + i);
    breg = *(const float4*)&W_o[bk * OUT_ + col0 + bn];

    float acc[4][4];
#pragma unroll
    for (int i = 0; i < 4; i++)
#pragma unroll
        for (int j = 0; j < 4; j++) acc[i][j] = 0.f;

    const int nk = KTOT / 16;   // 136
    for (int kb = 0; kb < nk; kb++) {
        const int cur = kb & 1;
#pragma unroll
        for (int i = 0; i < 4; i++) As[cur][(ak + i) * 68 + am] = areg[i];
        *(float4*)&Bs[cur][bk * 68 + bn] = breg;
        __syncthreads();

        if (kb + 1 < nk) {
            const int k0 = (kb + 1) * 16;
#pragma unroll
            for (int i = 0; i < 4; i++) areg[i] = loadA(x, row0 + am, k0 + ak + i);
            breg = *(const float4*)&W_o[(k0 + bk) * OUT_ + col0 + bn];
        }

#pragma unroll
        for (int k = 0; k < 16; k++) {
            float4 a  = *(const float4*)&As[cur][k * 68 + ty * 4];
            float4 bb = *(const float4*)&Bs[cur][k * 68 + tx * 4];
            acc[0][0] = fmaf(a.x, bb.x, acc[0][0]);
            acc[0][1] = fmaf(a.x, bb.y, acc[0][1]);
            acc[0][2] = fmaf(a.x, bb.z, acc[0][2]);
            acc[0][3] = fmaf(a.x, bb.w, acc[0][3]);
            acc[1][0] = fmaf(a.y, bb.x, acc[1][0]);
            acc[1][1] = fmaf(a.y, bb.y, acc[1][1]);
            acc[1][2] = fmaf(a.y, bb.z, acc[1][2]);
            acc[1][3] = fmaf(a.y, bb.w, acc[1][3]);
            acc[2][0] = fmaf(a.z, bb.x, acc[2][0]);
            acc[2][1] = fmaf(a.z, bb.y, acc[2][1]);
            acc[2][2] = fmaf(a.z, bb.z, acc[2][2]);
            acc[2][3] = fmaf(a.z, bb.w, acc[2][3]);
            acc[3][0] = fmaf(a.w, bb.x, acc[3][0]);
            acc[3][1] = fmaf(a.w, bb.y, acc[3][1]);
            acc[3][2] = fmaf(a.w, bb.z, acc[3][2]);
            acc[3][3] = fmaf(a.w, bb.w, acc[3][3]);
        }
        __syncthreads();
    }

    const float4 bo = *(const float4*)&b_o[col0 + tx * 4];
#pragma unroll
    for (int i = 0; i < 4; i++) {
        const int r = row0 + ty * 4 + i;
        float4 v;
        v.x = acc[i][0] + bo.x;
        v.y = acc[i][1] + bo.y;
        v.z = acc[i][2] + bo.z;
        v.w = acc[i][3] + bo.w;
        *(float4*)&out[r * OUT_ + col0 + tx * 4] = v;
    }
}

// ============================================================================
// launch
// Inputs (metadata order): x, memory, W_ar, b_ar, W_pr, b_pr, W_f, b_f,
//                          W_r, b_r, W_o, b_o
// Output layout: output[512*2048] then new_memory[512*128*64]
// ============================================================================
extern "C" void kernel_launch(void* const* d_in, const int* in_sizes, int n_in,
                              void* d_out, int out_size) {
    const float* x      = (const float*)d_in[0];
    const float* memory = (const float*)d_in[1];
    const float* W_ar   = (const float*)d_in[2];
    const float* b_ar   = (const float*)d_in[3];
    const float* W_pr   = (const float*)d_in[4];
    const float* b_pr   = (const float*)d_in[5];
    const float* W_f    = (const float*)d_in[6];
    const float* b_f    = (const float*)d_in[7];
    const float* W_r    = (const float*)d_in[8];
    const float* b_r    = (const float*)d_in[9];
    const float* W_o    = (const float*)d_in[10];
    const float* b_o    = (const float*)d_in[11];

    float* out     = (float*)d_out;
    float* new_mem = out + (size_t)BB * OUT_;

    static bool attr_set = false;
    if (!attr_set) {
        cudaFuncSetAttribute(k2_kernel, cudaFuncAttributeMaxDynamicSharedMemorySize, K2_SMEM);
        attr_set = true;
    }

    pack_kernel<<<(IN_ * NCOLS + 255) / 256, 256>>>(W_ar, W_r, W_f);
    k1_kernel<<<dim3(16, 16), 160>>>(x);
    k2_kernel<<<BB, 128, K2_SMEM>>>(memory, b_ar, W_pr, b_pr, W_f, b_f, W_r, b_r, new_mem);
    k3_kernel<<<dim3(32, 8), 256>>>(x, W_o, b_o, out);
}

// round 7
// speedup vs baseline: 1.5875x; 1.5875x over previous
#include <cuda_runtime.h>
#include <cuda_bf16.h>
#include <math.h>
#include <stdint.h>

// Shapes (fixed by the problem)
#define BB     512
#define NSLOT  128
#define IN_    2048
#define MEM_   64
#define OUT_   2048
#define KTOT   2176   // IN + 2*MEM
#define NK1    16     // split-K factor for K1
#define NCOLS  130    // 64 (q) + 65 (xr) + 1 (xf)

// -------------------- device scratch (no allocations allowed) ----------------
__device__ float g_kpart[NK1 * BB * NCOLS];   // K1 partial sums
__device__ float g_wpack[IN_ * NCOLS];        // packed [W_ar | W_r_x | W_f_x]
__device__ float g_ar[BB * MEM_];             // active recall
__device__ float g_pr[BB * MEM_];             // passive recall

// bf16 split operands for tensor-core K3
__device__ __nv_bfloat16 g_ahi[BB * KTOT];      // A = [x | ar | pr] hi
__device__ __nv_bfloat16 g_alo[BB * KTOT];      // A lo
__device__ __nv_bfloat16 g_bhi[OUT_ * KTOT];    // W_o^T hi  (N-major rows, K contiguous)
__device__ __nv_bfloat16 g_blo[OUT_ * KTOT];    // W_o^T lo

// ============================================================================
// PTX helpers (base compute_103 compatible: ldmatrix / mma.sync / cp.async)
// ============================================================================
__device__ __forceinline__ uint32_t smem_u32(const void* p) {
    uint32_t a;
    asm("{ .reg .u64 t; cvta.to.shared.u64 t, %1; cvt.u32.u64 %0, t; }" : "=r"(a) : "l"(p));
    return a;
}

__device__ __forceinline__ void ldsm4(uint32_t* r, uint32_t addr) {
    asm volatile("ldmatrix.sync.aligned.m8n8.x4.shared.b16 {%0,%1,%2,%3}, [%4];"
        : "=r"(r[0]), "=r"(r[1]), "=r"(r[2]), "=r"(r[3]) : "r"(addr));
}

__device__ __forceinline__ void mma16816(float* d, const uint32_t* a, const uint32_t* b) {
    asm volatile("mma.sync.aligned.m16n8k16.row.col.f32.bf16.bf16.f32 "
        "{%0,%1,%2,%3}, {%4,%5,%6,%7}, {%8,%9}, {%0,%1,%2,%3};"
        : "+f"(d[0]), "+f"(d[1]), "+f"(d[2]), "+f"(d[3])
        : "r"(a[0]), "r"(a[1]), "r"(a[2]), "r"(a[3]), "r"(b[0]), "r"(b[1]));
}

__device__ __forceinline__ void cpasync16(uint32_t smem, const void* g) {
    asm volatile("cp.async.cg.shared.global [%0], [%1], 16;" :: "r"(smem), "l"(g));
}
#define CP_COMMIT() asm volatile("cp.async.commit_group;" ::: "memory")
#define CP_WAIT1()  asm volatile("cp.async.wait_group 1;" ::: "memory")
#define CP_WAIT0()  asm volatile("cp.async.wait_group 0;" ::: "memory")

// ============================================================================
// K0: pack the x-side weight columns into one contiguous [2048 x 130] matrix
// ============================================================================
__global__ void pack_kernel(const float* __restrict__ W_ar,
                            const float* __restrict__ W_r,
                            const float* __restrict__ W_f) {
    int idx = blockIdx.x * 256 + threadIdx.x;
    if (idx >= IN_ * NCOLS) return;
    int k = idx / NCOLS;
    int j = idx - k * NCOLS;
    float w;
    if (j < 64)       w = W_ar[k * 64 + j];
    else if (j < 129) w = W_r[k * 65 + (j - 64)];
    else              w = W_f[k];
    g_wpack[idx] = w;
}

// ============================================================================
// K1: partial GEMM  x[512,2048] @ wpack[2048,130] -> g_kpart[16][512][130]
// ============================================================================
__global__ void k1_kernel(const float* __restrict__ x) {
    const int mb = blockIdx.x;
    const int kb = blockIdx.y;
    __shared__ float xs[32][128];

    for (int i = threadIdx.x; i < 32 * 128; i += blockDim.x) {
        int m = i >> 7, k = i & 127;
        xs[m][k] = x[(mb * 32 + m) * IN_ + kb * 128 + k];
    }
    __syncthreads();

    const int j = threadIdx.x;
    if (j < NCOLS) {
        float acc[32];
#pragma unroll
        for (int m = 0; m < 32; m++) acc[m] = 0.f;
        const float* wp = g_wpack + (kb * 128) * NCOLS + j;
#pragma unroll 4
        for (int k = 0; k < 128; k++) {
            float w = wp[k * NCOLS];
#pragma unroll
            for (int m = 0; m < 32; m++) acc[m] = fmaf(xs[m][k], w, acc[m]);
        }
        float* outp = g_kpart + (kb * BB + mb * 32) * NCOLS + j;
#pragma unroll
        for (int m = 0; m < 32; m++) outp[m * NCOLS] = acc[m];
    }
}

// ============================================================================
// K2: per-batch fused attention/softmax/recalls + gated memory update
// ============================================================================
#define K2_SMEM ((NSLOT * 65 + 64 * 68) * 4)   // 50688 bytes

__global__ void k2_kernel(const float* __restrict__ memory,
                          const float* __restrict__ b_ar,
                          const float* __restrict__ W_pr,
                          const float* __restrict__ b_pr,
                          const float* __restrict__ W_f,
                          const float* __restrict__ b_f,
                          const float* __restrict__ W_r,
                          const float* __restrict__ b_r,
                          float* __restrict__ new_memory) {
    extern __shared__ float dyn[];
    float* mem_s = dyn;                       // [128][65]
    float* wrm   = dyn + NSLOT * 65;          // [64][68]

    __shared__ float sq[64];
    __shared__ float sxr[65];
    __shared__ float swfm[64];
    __shared__ float swpr[64];
    __shared__ float sscore[128];
    __shared__ float sp[128];
    __shared__ float red[128];
    __shared__ float sxf;

    const int b = blockIdx.x;
    const int t = threadIdx.x;

    for (int jj = t; jj < NCOLS; jj += 128) {
        float s = 0.f;
#pragma unroll
        for (int kb = 0; kb < NK1; kb++) s += g_kpart[(kb * BB + b) * NCOLS + jj];
        if (jj < 64)       sq[jj] = s + b_ar[jj];
        else if (jj < 129) sxr[jj - 64] = s + b_r[jj - 64];
        else               sxf = s + b_f[0];
    }

    for (int i = t; i < 64 * 68; i += 128) {
        int k = i / 68, c = i - k * 68;
        wrm[i] = (c < 65) ? W_r[IN_ * 65 + k * 65 + c] : 0.f;
    }
    if (t < 64) { swfm[t] = W_f[IN_ + t]; swpr[t] = W_pr[t]; }

    const float* mrow = memory + (size_t)b * (NSLOT * MEM_);
    for (int i = t; i < NSLOT * MEM_; i += 128)
        mem_s[(i >> 6) * 65 + (i & 63)] = mrow[i];
    __syncthreads();

    const float* my = mem_s + t * 65;
    float sc = 0.f, pl = 0.f;
#pragma unroll
    for (int k = 0; k < 64; k++) {
        float mv = my[k];
        sc = fmaf(mv, sq[k], sc);
        pl = fmaf(mv, swpr[k], pl);
    }
    pl += b_pr[0];

    red[t] = sc; __syncthreads();
    for (int s2 = 64; s2 > 0; s2 >>= 1) { if (t < s2) red[t] = fmaxf(red[t], red[t + s2]); __syncthreads(); }
    float mx = red[0]; __syncthreads();
    float e = expf(sc - mx);
    red[t] = e; __syncthreads();
    for (int s2 = 64; s2 > 0; s2 >>= 1) { if (t < s2) red[t] += red[t + s2]; __syncthreads(); }
    sscore[t] = e / red[0]; __syncthreads();

    red[t] = pl; __syncthreads();
    for (int s2 = 64; s2 > 0; s2 >>= 1) { if (t < s2) red[t] = fmaxf(red[t], red[t + s2]); __syncthreads(); }
    float mx2 = red[0]; __syncthreads();
    float e2 = expf(pl - mx2);
    red[t] = e2; __syncthreads();
    for (int s2 = 64; s2 > 0; s2 >>= 1) { if (t < s2) red[t] += red[t + s2]; __syncthreads(); }
    sp[t] = e2 / red[0];
    __syncthreads();

    if (t < 64) {
        float a = 0.f, p = 0.f;
#pragma unroll 4
        for (int n = 0; n < NSLOT; n++) {
            float mv = mem_s[n * 65 + t];
            a = fmaf(mv, sscore[n], a);
            p = fmaf(mv, sp[n], p);
        }
        g_ar[b * 64 + t] = a;
        g_pr[b * 64 + t] = p;
    }

    float mreg[64];
#pragma unroll
    for (int k = 0; k < 64; k++) mreg[k] = my[k];

    float fl = sxf;
#pragma unroll
    for (int k = 0; k < 64; k++) fl = fmaf(mreg[k], swfm[k], fl);
    float fgt = 1.1f / (1.f + expf(-fl));

    float r64 = sxr[64];
#pragma unroll
    for (int k = 0; k < 64; k++) r64 = fmaf(mreg[k], wrm[k * 68 + 64], r64);

    __syncthreads();

    for (int jb = 0; jb < 16; jb++) {
        float a0 = sxr[jb * 4 + 0], a1 = sxr[jb * 4 + 1];
        float a2 = sxr[jb * 4 + 2], a3 = sxr[jb * 4 + 3];
#pragma unroll
        for (int k = 0; k < 64; k++) {
            float4 w = *(const float4*)&wrm[k * 68 + jb * 4];
            float mv = mreg[k];
            a0 = fmaf(mv, w.x, a0);
            a1 = fmaf(mv, w.y, a1);
            a2 = fmaf(mv, w.z, a2);
            a3 = fmaf(mv, w.w, a3);
        }
        mem_s[t * 65 + jb * 4 + 0] = fmaf(mreg[jb * 4 + 0], fgt, r64 * a0);
        mem_s[t * 65 + jb * 4 + 1] = fmaf(mreg[jb * 4 + 1], fgt, r64 * a1);
        mem_s[t * 65 + jb * 4 + 2] = fmaf(mreg[jb * 4 + 2], fgt, r64 * a2);
        mem_s[t * 65 + jb * 4 + 3] = fmaf(mreg[jb * 4 + 3], fgt, r64 * a3);
    }
    __syncthreads();

    float* orow = new_memory + (size_t)b * (NSLOT * MEM_);
    for (int i = t; i < NSLOT * MEM_; i += 128)
        orow[i] = mem_s[(i >> 6) * 65 + (i & 63)];
}

// ============================================================================
// convA: build bf16 hi/lo of A = [x | ar | pr]  (512 x 2176)
// ============================================================================
__global__ void convA_kernel(const float* __restrict__ x) {
    int i = blockIdx.x * 256 + threadIdx.x;
    if (i >= BB * KTOT) return;
    int m = i / KTOT, k = i - m * KTOT;
    float v;
    if (k < IN_)              v = x[m * IN_ + k];
    else if (k < IN_ + MEM_)  v = g_ar[m * MEM_ + (k - IN_)];
    else                      v = g_pr[m * MEM_ + (k - IN_ - MEM_)];
    __nv_bfloat16 h = __float2bfloat16(v);
    g_ahi[i] = h;
    g_alo[i] = __float2bfloat16(v - __bfloat162float(h));
}

// ============================================================================
// convB: transpose + bf16 split of W_o: g_b*[n][k] = split(W_o[k][n])
// ============================================================================
__global__ void convB_kernel(const float* __restrict__ W_o) {
    __shared__ float t[32][33];
    const int nb = blockIdx.x;   // 64 n-tiles
    const int kb = blockIdx.y;   // 68 k-tiles
    const int tx = threadIdx.x & 31, ty = threadIdx.x >> 5;  // 256 thr

    for (int r = ty; r < 32; r += 8)
        t[r][tx] = W_o[(kb * 32 + r) * OUT_ + nb * 32 + tx];
    __syncthreads();

    for (int r = ty; r < 32; r += 8) {
        float v = t[tx][r];   // k = kb*32+tx, n = nb*32+r
        __nv_bfloat16 h = __float2bfloat16(v);
        size_t o = (size_t)(nb * 32 + r) * KTOT + kb * 32 + tx;
        g_bhi[o] = h;
        g_blo[o] = __float2bfloat16(v - __bfloat162float(h));
    }
}

// ============================================================================
// K3: mma.sync bf16 3-split GEMM  D[512,2048] = A[512,2176] @ W_o + b_o
//     CTA tile 64(M) x 128(N), BK=32, 8 warps (warp tile 32x32),
//     cp.async double-buffered SMEM (rows padded to 80B: conflict-free LDSM).
// ============================================================================
#define BM     64
#define BN     128
#define BK     32
#define ROWB   80                       // 64B data + 16B pad per BK row
#define OFF_AHI 0
#define OFF_ALO (BM * ROWB)             // 5120
#define OFF_BHI (2 * BM * ROWB)         // 10240
#define OFF_BLO (OFF_BHI + BN * ROWB)   // 20480
#define STAGE_B (OFF_BLO + BN * ROWB)   // 30720
#define NKT    (KTOT / BK)              // 68
#define K3_SMEM (2 * STAGE_B + 512)

__device__ __forceinline__ void load_stage(uint32_t sbase, int row0, int col0,
                                           int kcol, int tid) {
    const int r = tid >> 2, c = tid & 3;
    {
        size_t gi = (size_t)(row0 + r) * KTOT + kcol + c * 8;
        cpasync16(sbase + OFF_AHI + r * ROWB + c * 16, g_ahi + gi);
        cpasync16(sbase + OFF_ALO + r * ROWB + c * 16, g_alo + gi);
    }
#pragma unroll
    for (int it = 0; it < 2; it++) {
        int i = tid + it * 256;
        int rb = i >> 2, cb = i & 3;
        size_t gi = (size_t)(col0 + rb) * KTOT + kcol + cb * 8;
        cpasync16(sbase + OFF_BHI + rb * ROWB + cb * 16, g_bhi + gi);
        cpasync16(sbase + OFF_BLO + rb * ROWB + cb * 16, g_blo + gi);
    }
}

__global__ void __launch_bounds__(256) k3_mma_kernel(const float* __restrict__ b_o,
                                                     float* __restrict__ out) {
    extern __shared__ char smem[];
    const uint32_t sb = smem_u32(smem);
    const int tid  = threadIdx.x;
    const int lane = tid & 31;
    const int wid  = tid >> 5;
    const int wm   = wid >> 2;       // 0..1
    const int wn   = wid & 3;        // 0..3
    const int row0 = blockIdx.y * BM;
    const int col0 = blockIdx.x * BN;

    float* bias_s = (float*)(smem + 2 * STAGE_B);
    if (tid < 128) bias_s[tid] = b_o[col0 + tid];

    float acc[2][4][4];
#pragma unroll
    for (int mi = 0; mi < 2; mi++)
#pragma unroll
        for (int ni = 0; ni < 4; ni++)
#pragma unroll
            for (int q = 0; q < 4; q++) acc[mi][ni][q] = 0.f;

    // ldmatrix per-lane offsets (row within tile, 16B segment)
    const int lrow = lane & 15;
    const int lseg = lane >> 4;
    const uint32_t aoff = (uint32_t)((wm * 32 + lrow) * ROWB + lseg * 16);
    const uint32_t boff = (uint32_t)((wn * 32 + lrow) * ROWB + lseg * 16);

    load_stage(sb, row0, col0, 0, tid);
    CP_COMMIT();

    for (int kt = 0; kt < NKT; kt++) {
        const uint32_t sbuf = sb + (uint32_t)(kt & 1) * STAGE_B;
        if (kt + 1 < NKT) {
            load_stage(sb + (uint32_t)((kt + 1) & 1) * STAGE_B, row0, col0, (kt + 1) * BK, tid);
            CP_COMMIT();
            CP_WAIT1();
        } else {
            CP_WAIT0();
        }
        __syncthreads();

#pragma unroll
        for (int kh = 0; kh < 2; kh++) {
            const uint32_t ko = (uint32_t)(kh * 32);
            uint32_t ah[2][4], al[2][4];
#pragma unroll
            for (int mi = 0; mi < 2; mi++) {
                ldsm4(ah[mi], sbuf + OFF_AHI + aoff + (uint32_t)(mi * 16 * ROWB) + ko);
                ldsm4(al[mi], sbuf + OFF_ALO + aoff + (uint32_t)(mi * 16 * ROWB) + ko);
            }
            uint32_t bh[4][2], bl[4][2];
#pragma unroll
            for (int ng = 0; ng < 2; ng++) {
                uint32_t r[4];
                ldsm4(r, sbuf + OFF_BHI + boff + (uint32_t)(ng * 16 * ROWB) + ko);
                bh[ng * 2 + 0][0] = r[0]; bh[ng * 2 + 0][1] = r[2];
                bh[ng * 2 + 1][0] = r[1]; bh[ng * 2 + 1][1] = r[3];
                ldsm4(r, sbuf + OFF_BLO + boff + (uint32_t)(ng * 16 * ROWB) + ko);
                bl[ng * 2 + 0][0] = r[0]; bl[ng * 2 + 0][1] = r[2];
                bl[ng * 2 + 1][0] = r[1]; bl[ng * 2 + 1][1] = r[3];
            }
#pragma unroll
            for (int mi = 0; mi < 2; mi++) {
#pragma unroll
                for (int ni = 0; ni < 4; ni++) {
                    mma16816(acc[mi][ni], ah[mi], bh[ni]);
                    mma16816(acc[mi][ni], ah[mi], bl[ni]);
                    mma16816(acc[mi][ni], al[mi], bh[ni]);
                }
            }
        }
        __syncthreads();
    }

    // epilogue: D frag rows = lane/4 (+8), cols = 2*(lane%4)
    const int er = lane >> 2;
    const int ec = (lane & 3) * 2;
#pragma unroll
    for (int mi = 0; mi < 2; mi++) {
#pragma unroll
        for (int ni = 0; ni < 4; ni++) {
            const int row = row0 + wm * 32 + mi * 16 + er;
            const int lc  = wn * 32 + ni * 8 + ec;
            const int col = col0 + lc;
            float2 v0, v1;
            v0.x = acc[mi][ni][0] + bias_s[lc];
            v0.y = acc[mi][ni][1] + bias_s[lc + 1];
            v1.x = acc[mi][ni][2] + bias_s[lc];
            v1.y = acc[mi][ni][3] + bias_s[lc + 1];
            *(float2*)&out[(size_t)row * OUT_ + col] = v0;
            *(float2*)&out[(size_t)(row + 8) * OUT_ + col] = v1;
        }
    }
}

// ============================================================================
// launch
// ============================================================================
extern "C" void kernel_launch(void* const* d_in, const int* in_sizes, int n_in,
                              void* d_out, int out_size) {
    const float* x      = (const float*)d_in[0];
    const float* memory = (const float*)d_in[1];
    const float* W_ar   = (const float*)d_in[2];
    const float* b_ar   = (const float*)d_in[3];
    const float* W_pr   = (const float*)d_in[4];
    const float* b_pr   = (const float*)d_in[5];
    const float* W_f    = (const float*)d_in[6];
    const float* b_f    = (const float*)d_in[7];
    const float* W_r    = (const float*)d_in[8];
    const float* b_r    = (const float*)d_in[9];
    const float* W_o    = (const float*)d_in[10];
    const float* b_o    = (const float*)d_in[11];

    float* out     = (float*)d_out;
    float* new_mem = out + (size_t)BB * OUT_;

    cudaFuncSetAttribute(k2_kernel,     cudaFuncAttributeMaxDynamicSharedMemorySize, K2_SMEM);
    cudaFuncSetAttribute(k3_mma_kernel, cudaFuncAttributeMaxDynamicSharedMemorySize, K3_SMEM);

    pack_kernel<<<(IN_ * NCOLS + 255) / 256, 256>>>(W_ar, W_r, W_f);
    convB_kernel<<<dim3(OUT_ / 32, KTOT / 32), 256>>>(W_o);
    k1_kernel<<<dim3(16, 16), 160>>>(x);
    k2_kernel<<<BB, 128, K2_SMEM>>>(memory, b_ar, W_pr, b_pr, W_f, b_f, W_r, b_r, new_mem);
    convA_kernel<<<(BB * KTOT + 255) / 256, 256>>>(x);
    k3_mma_kernel<<<dim3(OUT_ / BN, BB / BM), 256, K3_SMEM>>>(b_o, out);
}